// round 5
// baseline (speedup 1.0000x reference)
#include <cuda_runtime.h>
#include <cuda_fp16.h>
#include <cstdint>

#define BB 64
#define NN 512
#define CC 1024
#define KC 32
#define NCH (CC/KC)          // 32 k-chunks

// Scratch (allocation-free rule: __device__ globals)
__device__ float  g_S[(size_t)BB * NN * NN];          // 67 MB
__device__ __half g_H1[(size_t)BB * NN * CC];         // 67 MB  x = h1 + h2
__device__ __half g_H2[(size_t)BB * NN * CC];         // 67 MB
__device__ float  g_thr[BB * NN];
__device__ float  g_rdeg[BB * NN];

// smem tiles: 4 tiles (A1,A2,B1,B2) x 128 rows x 32 halves, row stride 80 B
#define ROWB   80
#define TILE_B (128 * ROWB)          // 10240
#define BUF_B  (4 * TILE_B)          // 40960
#define SMEM_TOTAL (2 * BUF_B)       // 81920  (also reused for mirror transpose)

__device__ __forceinline__ uint32_t smem_u32(const void* p) {
    uint32_t a;
    asm("{ .reg .u64 t; cvta.to.shared.u64 t, %1; cvt.u32.u64 %0, t; }"
        : "=r"(a) : "l"(p));
    return a;
}
__device__ __forceinline__ void cp16(uint32_t dst, const void* src) {
    asm volatile("cp.async.cg.shared.global [%0], [%1], 16;"
                 :: "r"(dst), "l"(src));
}
__device__ __forceinline__ void cp_commit() {
    asm volatile("cp.async.commit_group;" ::: "memory");
}
__device__ __forceinline__ void cp_wait1() {
    asm volatile("cp.async.wait_group 1;" ::: "memory");
}
__device__ __forceinline__ void cp_wait0() {
    asm volatile("cp.async.wait_group 0;" ::: "memory");
}
__device__ __forceinline__ void ldsm4(uint32_t& r0, uint32_t& r1,
                                      uint32_t& r2, uint32_t& r3, uint32_t a) {
    asm volatile("ldmatrix.sync.aligned.m8n8.x4.shared.b16 {%0,%1,%2,%3}, [%4];"
                 : "=r"(r0), "=r"(r1), "=r"(r2), "=r"(r3) : "r"(a));
}
__device__ __forceinline__ void mma16816(float* d, const uint32_t* a,
                                         uint32_t b0, uint32_t b1) {
    asm volatile(
        "mma.sync.aligned.m16n8k16.row.col.f32.f16.f16.f32 "
        "{%0,%1,%2,%3}, {%4,%5,%6,%7}, {%8,%9}, {%0,%1,%2,%3};"
        : "+f"(d[0]), "+f"(d[1]), "+f"(d[2]), "+f"(d[3])
        : "r"(a[0]), "r"(a[1]), "r"(a[2]), "r"(a[3]), "r"(b0), "r"(b1));
}

// ---------------------------------------------------------------------------
// Kernel 0: fp32 -> (h1, h2) split planes.  x = h1 + h2 exactly to ~22 bits.
// ---------------------------------------------------------------------------
__global__ __launch_bounds__(256)
void convert_kernel(const float* __restrict__ X)
{
    const size_t i = (size_t)blockIdx.x * blockDim.x + threadIdx.x; // float4 idx
    float4 v = ((const float4*)X)[i];
    __half2 a1 = __floats2half2_rn(v.x, v.y);
    __half2 b1 = __floats2half2_rn(v.z, v.w);
    float2 fa = __half22float2(a1);
    float2 fb = __half22float2(b1);
    __half2 a2 = __floats2half2_rn(v.x - fa.x, v.y - fa.y);
    __half2 b2 = __floats2half2_rn(v.z - fb.x, v.w - fb.y);
    ((uint2*)g_H1)[i] = make_uint2(*(uint32_t*)&a1, *(uint32_t*)&b1);
    ((uint2*)g_H2)[i] = make_uint2(*(uint32_t*)&a2, *(uint32_t*)&b2);
}

// ---------------------------------------------------------------------------
// Kernel A: HMMA split-fp16 GEMM.  S = H1 H1^T + H1 H2^T + H2 H1^T.
// cp.async loads (no register staging), 2 CTAs/SM, sequential MMA streams
// to keep regs <= 128.  Mirror writes staged via smem transpose.
// ---------------------------------------------------------------------------
__global__ __launch_bounds__(256, 2)
void gemm_mma_kernel()
{
    extern __shared__ __align__(16) char smem[];
    const unsigned char ITm[10] = {0,0,0,0,1,1,1,2,2,3};
    const unsigned char JTm[10] = {0,1,2,3,1,2,3,2,3,3};
    const int it = ITm[blockIdx.x];
    const int jt = JTm[blockIdx.x];
    const int b  = blockIdx.y;
    const int rbase = it * 128;
    const int cbase = jt * 128;

    const int tid  = threadIdx.x;
    const int wid  = tid >> 5;
    const int lane = tid & 31;
    const int wm   = wid >> 2;       // 0..1 -> 64-row slab
    const int wn   = wid & 3;        // 0..3 -> 32-col slab
    const uint32_t sb = smem_u32(smem);

    const __half* __restrict__ H1 = g_H1 + (size_t)b * NN * CC;
    const __half* __restrict__ H2 = g_H2 + (size_t)b * NN * CC;

    float acc[4][4][4];
    #pragma unroll
    for (int f = 0; f < 4; f++)
        #pragma unroll
        for (int n = 0; n < 4; n++)
            #pragma unroll
            for (int q = 0; q < 4; q++) acc[f][n][q] = 0.0f;

    // cp.async one 32-deep chunk into buffer bs: 2048 16B units, 8/thread
    auto issue = [&](int k0, int bs) {
        #pragma unroll
        for (int i = 0; i < 8; i++) {
            int u  = i * 256 + tid;          // 0..2047
            int t2 = u >> 9;                 // 0=A1,1=A2,2=B1,3=B2
            int w  = u & 511;
            int r  = w >> 2;                 // 0..127
            int uc = w & 3;                  // 16B unit in row
            const __half* plane = (t2 & 1) ? H2 : H1;
            int blk = (t2 < 2) ? rbase : cbase;
            const __half* src = plane + (size_t)(blk + r) * CC + k0 + uc * 8;
            uint32_t dst = sb + bs * BUF_B + t2 * TILE_B + r * ROWB + uc * 16;
            cp16(dst, src);
        }
        cp_commit();
    };

    issue(0, 0);

    const int lrow = lane & 15;
    const int lcol = (lane >> 4) * 16;

    #pragma unroll 1
    for (int c = 0; c < NCH; c++) {
        const int bs = c & 1;
        if (c + 1 < NCH) { issue((c + 1) * KC, bs ^ 1); cp_wait1(); }
        else             { cp_wait0(); }
        __syncthreads();

        const uint32_t tb  = sb + bs * BUF_B;
        const uint32_t pA1 = tb;
        const uint32_t pA2 = tb + TILE_B;
        const uint32_t pB1 = tb + 2 * TILE_B;
        const uint32_t pB2 = tb + 3 * TILE_B;

        #pragma unroll
        for (int ks = 0; ks < 2; ks++) {
            const int kb = ks * 32;          // 16 halves = 32 B
            uint32_t af[4][4], bf[2][4], bg[2][4];
            // A1 frags
            #pragma unroll
            for (int f = 0; f < 4; f++) {
                uint32_t ad = (wm * 64 + f * 16 + lrow) * ROWB + lcol + kb;
                ldsm4(af[f][0], af[f][1], af[f][2], af[f][3], pA1 + ad);
            }
            // B1 frags
            #pragma unroll
            for (int g = 0; g < 2; g++) {
                uint32_t ad = (wn * 32 + g * 16 + lrow) * ROWB + lcol + kb;
                ldsm4(bf[g][0], bf[g][1], bf[g][2], bf[g][3], pB1 + ad);
            }
            // stream H1 x H1
            #pragma unroll
            for (int f = 0; f < 4; f++)
                #pragma unroll
                for (int g = 0; g < 2; g++)
                    #pragma unroll
                    for (int h = 0; h < 2; h++)
                        mma16816(acc[f][g*2+h], af[f], bf[g][0+h], bf[g][2+h]);
            // B2 frags; stream H1 x H2
            #pragma unroll
            for (int g = 0; g < 2; g++) {
                uint32_t ad = (wn * 32 + g * 16 + lrow) * ROWB + lcol + kb;
                ldsm4(bg[g][0], bg[g][1], bg[g][2], bg[g][3], pB2 + ad);
            }
            #pragma unroll
            for (int f = 0; f < 4; f++)
                #pragma unroll
                for (int g = 0; g < 2; g++)
                    #pragma unroll
                    for (int h = 0; h < 2; h++)
                        mma16816(acc[f][g*2+h], af[f], bg[g][0+h], bg[g][2+h]);
            // A2 frags (overwrite af); stream H2 x H1
            #pragma unroll
            for (int f = 0; f < 4; f++) {
                uint32_t ad = (wm * 64 + f * 16 + lrow) * ROWB + lcol + kb;
                ldsm4(af[f][0], af[f][1], af[f][2], af[f][3], pA2 + ad);
            }
            #pragma unroll
            for (int f = 0; f < 4; f++)
                #pragma unroll
                for (int g = 0; g < 2; g++)
                    #pragma unroll
                    for (int h = 0; h < 2; h++)
                        mma16816(acc[f][g*2+h], af[f], bf[g][0+h], bf[g][2+h]);
        }
        __syncthreads();   // protect buffer before next issue overwrites it
    }

    // ---- epilogue ----
    float* __restrict__ Sb = g_S + (size_t)b * NN * NN;
    const int r0 = lane >> 2;
    const int c0 = (lane & 3) * 2;

    // direct (coalesced) stores
    #pragma unroll
    for (int f = 0; f < 4; f++) {
        const int gr = rbase + wm * 64 + f * 16 + r0;
        #pragma unroll
        for (int n = 0; n < 4; n++) {
            const int gc = cbase + wn * 32 + n * 8 + c0;
            float* d = acc[f][n];
            *(float2*)&Sb[(size_t)gr * NN + gc]       = make_float2(d[0], d[1]);
            *(float2*)&Sb[(size_t)(gr + 8) * NN + gc] = make_float2(d[2], d[3]);
        }
    }

    // mirror via smem transpose (coalesced on both sides)
    if (jt > it) {
        float* st = (float*)smem;            // 128 x 129 floats = 66048 B
        #pragma unroll
        for (int f = 0; f < 4; f++) {
            const int sr = wm * 64 + f * 16 + r0;
            #pragma unroll
            for (int n = 0; n < 4; n++) {
                const int sc = wn * 32 + n * 8 + c0;
                float* d = acc[f][n];
                st[(size_t)sr * 129 + sc]           = d[0];
                st[(size_t)sr * 129 + sc + 1]       = d[1];
                st[(size_t)(sr + 8) * 129 + sc]     = d[2];
                st[(size_t)(sr + 8) * 129 + sc + 1] = d[3];
            }
        }
        __syncthreads();
        const int mr = tid >> 1;            // mirror row = tile column
        const int hh = tid & 1;             // which 64-wide half
        float* dst = Sb + (size_t)(cbase + mr) * NN + rbase + hh * 64;
        #pragma unroll
        for (int i = 0; i < 16; i++) {
            float4 v;
            v.x = st[(size_t)(hh * 64 + i * 4 + 0) * 129 + mr];
            v.y = st[(size_t)(hh * 64 + i * 4 + 1) * 129 + mr];
            v.z = st[(size_t)(hh * 64 + i * 4 + 2) * 129 + mr];
            v.w = st[(size_t)(hh * 64 + i * 4 + 3) * 129 + mr];
            *(float4*)(dst + i * 4) = v;
        }
    }
}

// ---------------------------------------------------------------------------
// Kernel B: one WARP per row; exact 32nd-largest via bitwise radix select.
// ---------------------------------------------------------------------------
__global__ __launch_bounds__(256)
void topk_threshold_kernel()
{
    const int row  = blockIdx.x * 8 + (threadIdx.x >> 5);
    const int lane = threadIdx.x & 31;
    const float* __restrict__ Sr = g_S + (size_t)row * NN;

    uint32_t u[16];
    const float4* S4 = (const float4*)Sr;
    #pragma unroll
    for (int j = 0; j < 4; j++) {
        float4 t = S4[lane + 32 * j];
        float f[4] = {t.x, t.y, t.z, t.w};
        #pragma unroll
        for (int q = 0; q < 4; q++) {
            uint32_t s = __float_as_uint(f[q]);
            u[4*j+q] = (s & 0x80000000u) ? ~s : (s | 0x80000000u);
        }
    }

    uint32_t thr = 0;
    #pragma unroll 1
    for (int bit = 31; bit >= 0; bit--) {
        const uint32_t test = thr | (1u << bit);
        int c = 0;
        #pragma unroll
        for (int j = 0; j < 16; j++) c += (u[j] >= test);
        c = __reduce_add_sync(0xffffffffu, c);
        if (c >= 32) thr = test;
    }

    int cnt = 0;
    #pragma unroll
    for (int j = 0; j < 16; j++) cnt += (u[j] >= thr);
    cnt = __reduce_add_sync(0xffffffffu, cnt);

    if (lane == 0) {
        float tf = (thr & 0x80000000u) ? __uint_as_float(thr & 0x7fffffffu)
                                       : __uint_as_float(~thr);
        g_thr[row]  = tf;
        g_rdeg[row] = rsqrtf((float)cnt);
    }
}

// ---------------------------------------------------------------------------
// Kernel C: out[b,i,j] = (S >= thr_i) ? rdeg_i * rdeg_j : 0
// ---------------------------------------------------------------------------
__global__ __launch_bounds__(256)
void normalize_kernel(float* __restrict__ out)
{
    const size_t idx = (size_t)blockIdx.x * blockDim.x + threadIdx.x;
    const int j4  = (int)(idx % (NN / 4));
    const int row = (int)(idx / (NN / 4));
    const int b   = row / NN;

    const float thr = g_thr[row];
    const float ri  = g_rdeg[row];
    const float4 s  = *(const float4*)(g_S + (size_t)row * NN + j4 * 4);
    const float* rj = g_rdeg + b * NN + j4 * 4;

    float4 o;
    o.x = (s.x >= thr) ? ri * rj[0] : 0.0f;
    o.y = (s.y >= thr) ? ri * rj[1] : 0.0f;
    o.z = (s.z >= thr) ? ri * rj[2] : 0.0f;
    o.w = (s.w >= thr) ? ri * rj[3] : 0.0f;
    ((float4*)out)[idx] = o;
}

// ---------------------------------------------------------------------------
extern "C" void kernel_launch(void* const* d_in, const int* in_sizes, int n_in,
                              void* d_out, int out_size)
{
    const float* x = (const float*)d_in[0];
    float* out = (float*)d_out;

    const int nf4 = BB * NN * CC / 4;
    convert_kernel<<<nf4 / 256, 256>>>(x);

    cudaFuncSetAttribute(gemm_mma_kernel,
                         cudaFuncAttributeMaxDynamicSharedMemorySize, SMEM_TOTAL);
    dim3 gGemm(10, BB);
    gemm_mma_kernel<<<gGemm, 256, SMEM_TOTAL>>>();

    topk_threshold_kernel<<<BB * NN / 8, 256>>>();

    const int n4 = BB * NN * NN / 4;
    normalize_kernel<<<n4 / 256, 256>>>(out);
}

// round 6
// speedup vs baseline: 1.2173x; 1.2173x over previous
#include <cuda_runtime.h>
#include <cuda_fp16.h>
#include <cstdint>

#define BB 64
#define NN 512
#define CC 1024
#define KC 64
#define NCH (CC/KC)          // 16 k-chunks

// Scratch (allocation-free rule: __device__ globals)
__device__ float g_S[(size_t)BB * NN * NN];      // 67 MB gram matrices
__device__ float g_thr[BB * NN];
__device__ float g_rdeg[BB * NN];

// smem: 4 tiles per buffer (A1,A2,B1,B2), 128 rows x 64 halves,
// padded row stride 144 B (72 halves) for conflict-free ldmatrix.
#define ROWB   144
#define TILE_B (128 * ROWB)          // 18432
#define BUF_B  (4 * TILE_B)          // 73728
#define SMEM_TOTAL (2 * BUF_B)       // 147456

#define NTHR 384                     // 8 MMA warps + 4 producer warps

// named barriers: FULL0=1, FULL1=2, EMPTY0=3, EMPTY1=4
#define BAR_SYNC(id)   asm volatile("bar.sync %0, %1;"   :: "r"(id), "n"(NTHR) : "memory")
#define BAR_ARRIVE(id) asm volatile("bar.arrive %0, %1;" :: "r"(id), "n"(NTHR) : "memory")

__device__ __forceinline__ uint32_t smem_u32(const void* p) {
    uint32_t a;
    asm("{ .reg .u64 t; cvta.to.shared.u64 t, %1; cvt.u32.u64 %0, t; }"
        : "=r"(a) : "l"(p));
    return a;
}
__device__ __forceinline__ void ldsm4(uint32_t& r0, uint32_t& r1,
                                      uint32_t& r2, uint32_t& r3, uint32_t a) {
    asm volatile("ldmatrix.sync.aligned.m8n8.x4.shared.b16 {%0,%1,%2,%3}, [%4];"
                 : "=r"(r0), "=r"(r1), "=r"(r2), "=r"(r3) : "r"(a));
}
__device__ __forceinline__ void mma16816(float* d, const uint32_t* a,
                                         uint32_t b0, uint32_t b1) {
    asm volatile(
        "mma.sync.aligned.m16n8k16.row.col.f32.f16.f16.f32 "
        "{%0,%1,%2,%3}, {%4,%5,%6,%7}, {%8,%9}, {%0,%1,%2,%3};"
        : "+f"(d[0]), "+f"(d[1]), "+f"(d[2]), "+f"(d[3])
        : "r"(a[0]), "r"(a[1]), "r"(a[2]), "r"(a[3]), "r"(b0), "r"(b1));
}

// ---------------------------------------------------------------------------
// Kernel A: warp-specialized HMMA split-fp16 GEMM.
// S = H1 H1^T + H1 H2^T + H2 H1^T, fp32 accumulation (exact to ~2^-22).
// Warps 0-7: MMA consumers (R4's proven inner loop, full reg budget).
// Warps 8-11: producers (LDG fp32 -> split fp16 -> STS), double buffered
// via named-barrier FULL/EMPTY pairs so the tensor pipe never waits on
// conversion.  128x128 tile / CTA over 10 symmetric tile-pairs x 64 batches.
// ---------------------------------------------------------------------------
__global__ __launch_bounds__(NTHR, 1)
void gemm_ws_kernel(const float* __restrict__ X)
{
    extern __shared__ __align__(16) char smem[];
    const unsigned char ITm[10] = {0,0,0,0,1,1,1,2,2,3};
    const unsigned char JTm[10] = {0,1,2,3,1,2,3,2,3,3};
    const int it = ITm[blockIdx.x];
    const int jt = JTm[blockIdx.x];
    const int b  = blockIdx.y;
    const int rbase = it * 128;
    const int cbase = jt * 128;

    const int tid  = threadIdx.x;
    const int wid  = tid >> 5;
    const int lane = tid & 31;
    const uint32_t sb = smem_u32(smem);
    const float* __restrict__ Xb = X + (size_t)b * NN * CC;

    float acc[4][4][4];
    #pragma unroll
    for (int f = 0; f < 4; f++)
        #pragma unroll
        for (int n = 0; n < 4; n++)
            #pragma unroll
            for (int q = 0; q < 4; q++) acc[f][n][q] = 0.0f;

    if (wid >= 8) {
        // ---------------- producer warps ----------------
        const int ptid = tid - 256;          // 0..127
        #pragma unroll 1
        for (int c = 0; c < NCH; c++) {
            const int bs = c & 1;
            if (c >= 2) BAR_SYNC(3 + bs);    // wait EMPTY[bs]
            char* base = smem + bs * BUF_B;
            const int k0 = c * KC;
            #pragma unroll
            for (int i = 0; i < 32; i++) {
                int u  = i * 128 + ptid;     // 0..4095 16B-units
                int t  = u >> 11;            // 0=A rows, 1=B rows
                int r  = (u >> 4) & 127;
                int f4 = u & 15;
                int grow = (t ? cbase : rbase) + r;
                float4 v = *(const float4*)(Xb + (size_t)grow * CC + k0 + f4 * 4);
                __half2 a1 = __floats2half2_rn(v.x, v.y);
                __half2 b1 = __floats2half2_rn(v.z, v.w);
                float2 fa = __half22float2(a1);
                float2 fb = __half22float2(b1);
                __half2 a2 = __floats2half2_rn(v.x - fa.x, v.y - fa.y);
                __half2 b2 = __floats2half2_rn(v.z - fb.x, v.w - fb.y);
                int off = r * ROWB + f4 * 8;
                *(uint2*)(base + (t*2+0) * TILE_B + off) =
                    make_uint2(*(uint32_t*)&a1, *(uint32_t*)&b1);
                *(uint2*)(base + (t*2+1) * TILE_B + off) =
                    make_uint2(*(uint32_t*)&a2, *(uint32_t*)&b2);
            }
            BAR_ARRIVE(1 + bs);              // signal FULL[bs]
        }
    } else {
        // ---------------- MMA consumer warps ----------------
        const int wm = wid >> 2;             // 0..1  -> 64-row slab
        const int wn = wid & 3;              // 0..3  -> 32-col slab
        const int lrow = lane & 15;
        const int lcol = (lane >> 4) * 16;

        #pragma unroll 1
        for (int c = 0; c < NCH; c++) {
            const int bs = c & 1;
            BAR_SYNC(1 + bs);                // wait FULL[bs]

            const uint32_t tb  = sb + bs * BUF_B;
            const uint32_t pA1 = tb;
            const uint32_t pA2 = tb + TILE_B;
            const uint32_t pB1 = tb + 2 * TILE_B;
            const uint32_t pB2 = tb + 3 * TILE_B;

            #pragma unroll
            for (int ks = 0; ks < 4; ks++) {
                const int kb = ks * 32;      // 16 halves = 32 B
                uint32_t a1[4][4], a2[4][4], b1r[2][4], b2r[2][4];
                #pragma unroll
                for (int f = 0; f < 4; f++) {
                    uint32_t ad = (wm * 64 + f * 16 + lrow) * ROWB + lcol + kb;
                    ldsm4(a1[f][0], a1[f][1], a1[f][2], a1[f][3], pA1 + ad);
                    ldsm4(a2[f][0], a2[f][1], a2[f][2], a2[f][3], pA2 + ad);
                }
                #pragma unroll
                for (int g = 0; g < 2; g++) {
                    uint32_t ad = (wn * 32 + g * 16 + lrow) * ROWB + lcol + kb;
                    ldsm4(b1r[g][0], b1r[g][1], b1r[g][2], b1r[g][3], pB1 + ad);
                    ldsm4(b2r[g][0], b2r[g][1], b2r[g][2], b2r[g][3], pB2 + ad);
                }
                #pragma unroll
                for (int f = 0; f < 4; f++)
                    #pragma unroll
                    for (int g = 0; g < 2; g++)
                        #pragma unroll
                        for (int h = 0; h < 2; h++) {
                            float* d = acc[f][g*2+h];
                            mma16816(d, a1[f], b1r[g][0+h], b1r[g][2+h]);
                            mma16816(d, a1[f], b2r[g][0+h], b2r[g][2+h]);
                            mma16816(d, a2[f], b1r[g][0+h], b1r[g][2+h]);
                        }
            }
            BAR_ARRIVE(3 + bs);              // signal EMPTY[bs]
        }
    }

    __syncthreads();

    // ---- epilogue (consumer warps hold acc) ----
    float* __restrict__ Sb = g_S + (size_t)b * NN * NN;
    const int r0 = lane >> 2;
    const int c0 = (lane & 3) * 2;
    const int wm = wid >> 2;
    const int wn = wid & 3;

    if (wid < 8) {
        #pragma unroll
        for (int f = 0; f < 4; f++) {
            const int gr = rbase + wm * 64 + f * 16 + r0;
            #pragma unroll
            for (int n = 0; n < 4; n++) {
                const int gc = cbase + wn * 32 + n * 8 + c0;
                float* d = acc[f][n];
                *(float2*)&Sb[(size_t)gr * NN + gc]       = make_float2(d[0], d[1]);
                *(float2*)&Sb[(size_t)(gr + 8) * NN + gc] = make_float2(d[2], d[3]);
            }
        }
    }

    // mirror via smem transpose (coalesced both sides)
    if (jt > it) {
        float* st = (float*)smem;            // 128 x 129 floats = 66048 B
        if (wid < 8) {
            #pragma unroll
            for (int f = 0; f < 4; f++) {
                const int sr = wm * 64 + f * 16 + r0;
                #pragma unroll
                for (int n = 0; n < 4; n++) {
                    const int sc = wn * 32 + n * 8 + c0;
                    float* d = acc[f][n];
                    st[(size_t)sr * 129 + sc]           = d[0];
                    st[(size_t)sr * 129 + sc + 1]       = d[1];
                    st[(size_t)(sr + 8) * 129 + sc]     = d[2];
                    st[(size_t)(sr + 8) * 129 + sc + 1] = d[3];
                }
            }
        }
        __syncthreads();
        if (tid < 256) {
            const int mr = tid >> 1;         // mirror row = tile column
            const int hh = tid & 1;          // 64-wide half
            float* dst = Sb + (size_t)(cbase + mr) * NN + rbase + hh * 64;
            #pragma unroll
            for (int i = 0; i < 16; i++) {
                float4 v;
                v.x = st[(size_t)(hh * 64 + i * 4 + 0) * 129 + mr];
                v.y = st[(size_t)(hh * 64 + i * 4 + 1) * 129 + mr];
                v.z = st[(size_t)(hh * 64 + i * 4 + 2) * 129 + mr];
                v.w = st[(size_t)(hh * 64 + i * 4 + 3) * 129 + mr];
                *(float4*)(dst + i * 4) = v;
            }
        }
    }
}

// ---------------------------------------------------------------------------
// Kernel B: one WARP per row; exact 32nd-largest via bitwise radix select
// on monotone-mapped uint32 keys (REDUX counts), then degree.
// ---------------------------------------------------------------------------
__global__ __launch_bounds__(256)
void topk_threshold_kernel()
{
    const int row  = blockIdx.x * 8 + (threadIdx.x >> 5);
    const int lane = threadIdx.x & 31;
    const float* __restrict__ Sr = g_S + (size_t)row * NN;

    uint32_t u[16];
    const float4* S4 = (const float4*)Sr;
    #pragma unroll
    for (int j = 0; j < 4; j++) {
        float4 t = S4[lane + 32 * j];
        float f[4] = {t.x, t.y, t.z, t.w};
        #pragma unroll
        for (int q = 0; q < 4; q++) {
            uint32_t s = __float_as_uint(f[q]);
            u[4*j+q] = (s & 0x80000000u) ? ~s : (s | 0x80000000u);
        }
    }

    uint32_t thr = 0;
    #pragma unroll 1
    for (int bit = 31; bit >= 0; bit--) {
        const uint32_t test = thr | (1u << bit);
        int c = 0;
        #pragma unroll
        for (int j = 0; j < 16; j++) c += (u[j] >= test);
        c = __reduce_add_sync(0xffffffffu, c);
        if (c >= 32) thr = test;
    }

    int cnt = 0;
    #pragma unroll
    for (int j = 0; j < 16; j++) cnt += (u[j] >= thr);
    cnt = __reduce_add_sync(0xffffffffu, cnt);

    if (lane == 0) {
        float tf = (thr & 0x80000000u) ? __uint_as_float(thr & 0x7fffffffu)
                                       : __uint_as_float(~thr);
        g_thr[row]  = tf;
        g_rdeg[row] = rsqrtf((float)cnt);
    }
}

// ---------------------------------------------------------------------------
// Kernel C: out[b,i,j] = (S >= thr_i) ? rdeg_i * rdeg_j : 0
// ---------------------------------------------------------------------------
__global__ __launch_bounds__(256)
void normalize_kernel(float* __restrict__ out)
{
    const size_t idx = (size_t)blockIdx.x * blockDim.x + threadIdx.x;
    const int j4  = (int)(idx % (NN / 4));
    const int row = (int)(idx / (NN / 4));
    const int b   = row / NN;

    const float thr = g_thr[row];
    const float ri  = g_rdeg[row];
    const float4 s  = *(const float4*)(g_S + (size_t)row * NN + j4 * 4);
    const float* rj = g_rdeg + b * NN + j4 * 4;

    float4 o;
    o.x = (s.x >= thr) ? ri * rj[0] : 0.0f;
    o.y = (s.y >= thr) ? ri * rj[1] : 0.0f;
    o.z = (s.z >= thr) ? ri * rj[2] : 0.0f;
    o.w = (s.w >= thr) ? ri * rj[3] : 0.0f;
    ((float4*)out)[idx] = o;
}

// ---------------------------------------------------------------------------
extern "C" void kernel_launch(void* const* d_in, const int* in_sizes, int n_in,
                              void* d_out, int out_size)
{
    const float* x = (const float*)d_in[0];
    float* out = (float*)d_out;

    cudaFuncSetAttribute(gemm_ws_kernel,
                         cudaFuncAttributeMaxDynamicSharedMemorySize, SMEM_TOTAL);

    dim3 gGemm(10, BB);
    gemm_ws_kernel<<<gGemm, NTHR, SMEM_TOTAL>>>(x);

    topk_threshold_kernel<<<BB * NN / 8, 256>>>();

    const int n4 = BB * NN * NN / 4;
    normalize_kernel<<<n4 / 256, 256>>>(out);
}